// round 2
// baseline (speedup 1.0000x reference)
#include <cuda_runtime.h>
#include <math.h>

// ---------------------------------------------------------------------------
// RDAB block: x[16,64,128,128] fp32
// Round 2: dense 3x3 convs rewritten with packed fma.rn.f32x2 (FFMA2, 2x fp32
// FMA throughput on sm_103a, bit-exact fp32 per lane).
// ---------------------------------------------------------------------------

#define B_   16
#define C_   64
#define H_   128
#define W_   128
#define HW_  (H_*W_)
#define CHW_ (C_*HW_)

typedef unsigned long long u64;

// scratch (device globals: allocation-free per harness rules)
__device__ float g_buf1[(size_t)B_*CHW_];
__device__ float g_buf2[(size_t)B_*CHW_];
__device__ float g_gate[(size_t)B_*HW_];
__device__ float g_kern1[B_*C_*9];
__device__ float g_kern2[B_*C_*9];

__device__ __forceinline__ float leaky01(float v) {
    return v > 0.f ? v : 0.1f * v;
}

// packed f32x2 helpers
__device__ __forceinline__ u64 pk2(float lo, float hi) {
    u64 r; asm("mov.b64 %0, {%1,%2};" : "=l"(r) : "f"(lo), "f"(hi)); return r;
}
__device__ __forceinline__ void fma2(u64& d, u64 a, u64 b) {
    asm("fma.rn.f32x2 %0, %1, %2, %0;" : "+l"(d) : "l"(a), "l"(b));
}
__device__ __forceinline__ float2 unpk(u64 a) {
    float2 v; asm("mov.b64 {%0,%1}, %2;" : "=f"(v.x), "=f"(v.y) : "l"(a)); return v;
}

// ---------------------------------------------------------------------------
// 1) dynamic-kernel MLP:  hid = leaky(d @ k1);  kern = hid @ k2
// ---------------------------------------------------------------------------
__global__ void mlp_kernel(const float* __restrict__ d,
                           const float* __restrict__ k1a, const float* __restrict__ k2a,
                           const float* __restrict__ k1b, const float* __restrict__ k2b,
                           float* __restrict__ kern1, float* __restrict__ kern2)
{
    int b = blockIdx.x;
    int stage = blockIdx.y;
    const float* k1 = stage ? k1b : k1a;
    const float* k2 = stage ? k2b : k2a;
    float* ko = stage ? kern2 : kern1;

    __shared__ float dd[64];
    __shared__ float hid[64];
    int t = threadIdx.x;
    dd[t] = d[b*64 + t];
    __syncthreads();
    float s = 0.f;
#pragma unroll 8
    for (int i = 0; i < 64; i++) s += dd[i] * k1[i*64 + t];
    hid[t] = leaky01(s);
    __syncthreads();
#pragma unroll
    for (int r = 0; r < 9; r++) {
        int o = r*64 + t;
        float s2 = 0.f;
#pragma unroll 8
        for (int i = 0; i < 64; i++) s2 += hid[i] * k2[i*576 + o];
        ko[b*576 + o] = s2;
    }
}

// ---------------------------------------------------------------------------
// 2) gating map: M[b,h,w] = sigmoid( sum_c in[b,c,h,w]*cw[c] + cb )
// ---------------------------------------------------------------------------
__global__ void gate_kernel(const float* __restrict__ in,
                            const float* __restrict__ cw,
                            const float* __restrict__ cb,
                            float* __restrict__ M)
{
    __shared__ float scw[C_];
    if (threadIdx.x < C_) scw[threadIdx.x] = cw[threadIdx.x];
    __syncthreads();
    int idx = blockIdx.x * blockDim.x + threadIdx.x;
    int b  = idx / HW_;
    int hw = idx - b * HW_;
    const float* p = in + (size_t)b * CHW_ + hw;
    float s = cb[0];
#pragma unroll 8
    for (int c = 0; c < C_; c++) s += scw[c] * p[(size_t)c * HW_];
    M[idx] = 1.f / (1.f + expf(-s));
}

// ---------------------------------------------------------------------------
// 3) fused RDA: out = leaky( leaky(dwconv3x3(in,kern)) * M + in )
// ---------------------------------------------------------------------------
__global__ void rda_kernel(const float* __restrict__ in,
                           const float* __restrict__ kern,
                           const float* __restrict__ M,
                           float* __restrict__ out)
{
    int idx = blockIdx.x * blockDim.x + threadIdx.x;
    int c = blockIdx.y;
    int b = blockIdx.z;
    int h = idx >> 7;
    int w = idx & 127;

    const float* k = kern + (b*C_ + c) * 9;
    float k0 = k[0], k1 = k[1], k2 = k[2],
          k3 = k[3], k4 = k[4], k5 = k[5],
          k6 = k[6], k7 = k[7], k8 = k[8];

    const float* p = in + ((size_t)b*C_ + c) * HW_;
    float dw = 0.f;
    if (h > 0) {
        const float* r = p + (h-1)*W_;
        if (w > 0)    dw += k0 * r[w-1];
                      dw += k1 * r[w];
        if (w < 127)  dw += k2 * r[w+1];
    }
    {
        const float* r = p + h*W_;
        if (w > 0)    dw += k3 * r[w-1];
                      dw += k4 * r[w];
        if (w < 127)  dw += k5 * r[w+1];
    }
    if (h < 127) {
        const float* r = p + (h+1)*W_;
        if (w > 0)    dw += k6 * r[w-1];
                      dw += k7 * r[w];
        if (w < 127)  dw += k8 * r[w+1];
    }
    float v = leaky01(dw);
    float m = M[(size_t)b*HW_ + idx];
    v = v * m + p[h*W_ + w];
    out[((size_t)b*C_ + c) * HW_ + idx] = leaky01(v);
}

// ---------------------------------------------------------------------------
// 4) dense 3x3 conv 64->64 with packed f32x2 FMA.
//    Block: 128 threads (tw = tid&15 across w, th = tid>>4 across 8 rows).
//    Tile: 8 output rows x full W=128, COP=8 output channels.
//    Thread: 8 pixels (4 f32x2 pairs) x 8 oc = 32 packed accumulators.
//    grid = (16 h-tiles, 8 oc-groups, 16 batches)
// ---------------------------------------------------------------------------
#define COP 8

__global__ void __launch_bounds__(128, 4)
conv3x3_f32x2(const float* __restrict__ in,
              const float* __restrict__ wgt,
              const float* __restrict__ bias,
              const float* __restrict__ residual,   // may be null
              float* __restrict__ out,
              int apply_leaky)
{
    __shared__ float sRow[10][132];     // rows h0-1..h0+8, col j=0..129 (j=w+1), 5280 B
    __shared__ u64   sW2[C_ * COP * 9]; // duplicated weight pairs {q,q}, 36864 B

    int b   = blockIdx.z;
    int co0 = blockIdx.y * COP;
    int h0  = blockIdx.x * 8;
    int tid = threadIdx.x;
    int tw  = tid & 15;                 // 0..15, pixels 8*tw .. 8*tw+7
    int th  = tid >> 4;                 // 0..7, output row h0+th

    // stage duplicated weights once: sW2[ci*72 + oc*9 + tap] = {q,q}
    for (int i = tid; i < C_ * COP * 9; i += 128) {
        int ci  = i / 72;
        int rem = i - ci * 72;
        int oc  = rem / 9;
        int tap = rem - oc * 9;
        float q = wgt[((co0 + oc) * C_ + ci) * 9 + tap];
        sW2[i] = pk2(q, q);
    }

    u64 acc[COP][4];
#pragma unroll
    for (int oc = 0; oc < COP; oc++)
#pragma unroll
        for (int m = 0; m < 4; m++) acc[oc][m] = 0ull;

    const float* inb = in + (size_t)b * CHW_;

    for (int ci = 0; ci < C_; ci++) {
        __syncthreads();               // protect sRow from prior-iter readers
        const float* cp = inb + (size_t)ci * HW_;
        // load 10 halo rows x 130 cols; j = w+1
#pragma unroll
        for (int r = 0; r < 10; r++) {
            int gy = h0 - 1 + r;
            bool rowok = (gy >= 0) && (gy < H_);
            float v = 0.f;
            int w = tid - 1;                      // j = tid
            if (rowok && w >= 0) v = cp[gy * W_ + w];
            sRow[r][tid] = v;
            if (tid < 2) {                        // j = 128,129 <-> w = 127,128
                int w2 = 127 + tid;
                float v2 = 0.f;
                if (rowok && w2 < W_) v2 = cp[gy * W_ + w2];
                sRow[r][128 + tid] = v2;
            }
        }
        __syncthreads();

        const u64* wci = &sW2[ci * (COP * 9)];
#pragma unroll
        for (int r = 0; r < 3; r++) {
            const float* rp = &sRow[th + r][8 * tw];
            float4 a = *(const float4*)rp;        // j0..j3 (32B aligned)
            float4 c = *(const float4*)(rp + 4);  // j4..j7
            float2 e = *(const float2*)(rp + 8);  // j8,j9
            u64 P[9];                              // P[k] = {j_k, j_{k+1}}
            P[0] = pk2(a.x, a.y);  P[1] = pk2(a.y, a.z);
            P[2] = pk2(a.z, a.w);  P[3] = pk2(a.w, c.x);
            P[4] = pk2(c.x, c.y);  P[5] = pk2(c.y, c.z);
            P[6] = pk2(c.z, c.w);  P[7] = pk2(c.w, e.x);
            P[8] = pk2(e.x, e.y);
#pragma unroll
            for (int oc = 0; oc < COP; oc++) {
                const u64* wr = wci + oc * 9 + r * 3;
                u64 w0 = wr[0], w1 = wr[1], w2 = wr[2];
#pragma unroll
                for (int m = 0; m < 4; m++) {
                    fma2(acc[oc][m], P[2*m    ], w0);
                    fma2(acc[oc][m], P[2*m + 1], w1);
                    fma2(acc[oc][m], P[2*m + 2], w2);
                }
            }
        }
    }

    // epilogue: bias (+leaky) (+residual), store as float2
#pragma unroll
    for (int oc = 0; oc < COP; oc++) {
        float bv = bias[co0 + oc];
        size_t base = (((size_t)b * C_ + co0 + oc) * H_ + (h0 + th)) * W_ + 8 * tw;
#pragma unroll
        for (int m = 0; m < 4; m++) {
            float2 v = unpk(acc[oc][m]);
            v.x += bv; v.y += bv;
            if (apply_leaky) { v.x = leaky01(v.x); v.y = leaky01(v.y); }
            if (residual) {
                v.x += residual[base + 2*m];
                v.y += residual[base + 2*m + 1];
            }
            *(float2*)&out[base + 2*m] = v;
        }
    }
}

// ---------------------------------------------------------------------------
// launch
// ---------------------------------------------------------------------------
extern "C" void kernel_launch(void* const* d_in, const int* in_sizes, int n_in,
                              void* d_out, int out_size)
{
    const float* x       = (const float*)d_in[0];
    const float* d       = (const float*)d_in[1];
    const float* da1_k1  = (const float*)d_in[2];
    const float* da1_k2  = (const float*)d_in[3];
    const float* da1_cw  = (const float*)d_in[4];
    const float* da1_cb  = (const float*)d_in[5];
    const float* da2_k1  = (const float*)d_in[6];
    const float* da2_k2  = (const float*)d_in[7];
    const float* da2_cw  = (const float*)d_in[8];
    const float* da2_cb  = (const float*)d_in[9];
    const float* conv1_w = (const float*)d_in[10];
    const float* conv1_b = (const float*)d_in[11];
    const float* conv2_w = (const float*)d_in[12];
    const float* conv2_b = (const float*)d_in[13];
    float* out = (float*)d_out;

    float *buf1, *buf2, *gate, *kern1, *kern2;
    cudaGetSymbolAddress((void**)&buf1,  g_buf1);
    cudaGetSymbolAddress((void**)&buf2,  g_buf2);
    cudaGetSymbolAddress((void**)&gate,  g_gate);
    cudaGetSymbolAddress((void**)&kern1, g_kern1);
    cudaGetSymbolAddress((void**)&kern2, g_kern2);

    // 1) both dynamic-kernel MLPs
    mlp_kernel<<<dim3(B_, 2), 64>>>(d, da1_k1, da1_k2, da2_k1, da2_k2, kern1, kern2);

    // 2) gate1 from x
    gate_kernel<<<(B_*HW_)/256, 256>>>(x, da1_cw, da1_cb, gate);

    // 3) rda1: x -> buf1
    rda_kernel<<<dim3(HW_/256, C_, B_), 256>>>(x, kern1, gate, buf1);

    // 4) conv1 + leaky: buf1 -> buf2
    conv3x3_f32x2<<<dim3(16, C_/COP, B_), 128>>>(buf1, conv1_w, conv1_b, nullptr, buf2, 1);

    // 5) gate2 from buf2
    gate_kernel<<<(B_*HW_)/256, 256>>>(buf2, da2_cw, da2_cb, gate);

    // 6) rda2: buf2 -> buf1
    rda_kernel<<<dim3(HW_/256, C_, B_), 256>>>(buf2, kern2, gate, buf1);

    // 7) conv2 + residual(x): buf1 -> out
    conv3x3_f32x2<<<dim3(16, C_/COP, B_), 128>>>(buf1, conv2_w, conv2_b, x, out, 0);
}